// round 17
// baseline (speedup 1.0000x reference)
#include <cuda_runtime.h>
#include <cuda_bf16.h>
#include <math.h>
#include <stdint.h>

#define NN 50000
#define NE 800000

// ---------------- scratch (device globals; allocation-free rule) -----------
__device__ float g_bufA[NN * 64];
__device__ float g_bufB[NN * 64];
__device__ int   g_cnt[NN];
__device__ int   g_start[NN];
__device__ int   g_rank[NE];
__device__ int   g_total;
__device__ int2  g_edge[NE];   // packed (col, weight-bits)

// ---------------------------------------------------------------------------
// CSR build (rank-based, atomic-free scatter) — concurrent with GEMM1
// ---------------------------------------------------------------------------
__global__ void zero_cnt_kernel() {
    int i = blockIdx.x * blockDim.x + threadIdx.x;
    if (i < NN) g_cnt[i] = 0;
    if (i == 0) g_total = 0;
}

__global__ void hist_rank_kernel(const int* __restrict__ row) {
    int e = blockIdx.x * blockDim.x + threadIdx.x;
    if (e < NE) g_rank[e] = atomicAdd(&g_cnt[row[e]], 1);
}

__global__ __launch_bounds__(256) void offsets_kernel() {
    __shared__ int sp[256];
    __shared__ int base;
    const int t = threadIdx.x;
    const int r = blockIdx.x * 256 + t;
    int c = (r < NN) ? g_cnt[r] : 0;
    sp[t] = c;
    __syncthreads();
    #pragma unroll
    for (int off = 1; off < 256; off <<= 1) {
        int v = (t >= off) ? sp[t - off] : 0;
        __syncthreads();
        sp[t] += v;
        __syncthreads();
    }
    if (t == 255) base = atomicAdd(&g_total, sp[255]);
    __syncthreads();
    if (r < NN) g_start[r] = base + sp[t] - c;
}

__global__ void scatter_kernel(const int* __restrict__ row,
                               const int* __restrict__ col,
                               const float* __restrict__ ew) {
    int e = blockIdx.x * blockDim.x + threadIdx.x;
    if (e < NE) {
        int p = g_start[row[e]] + g_rank[e];
        g_edge[p] = make_int2(col[e], __float_as_int(ew[e]));
    }
}

// ---------------------------------------------------------------------------
// SpMM via CSR, warp per row, float4 gathers (halved LDG issue count).
// Two 16-lane groups per warp own alternating edges; each lane loads one
// float4 (4 features) of its group's edge row. Cross-group combine via shfl.
// D4 = float4s per row: 16 (D=64) or 10 (D=40).
// LOGSM: fuse log-softmax over D=40 into the epilogue.
// ---------------------------------------------------------------------------
template <int D4, bool LOGSM>
__global__ __launch_bounds__(256) void spmm_csr_kernel(
    const float4* __restrict__ sup, float4* __restrict__ out)
{
    int warp = (blockIdx.x * blockDim.x + threadIdx.x) >> 5;
    if (warp >= NN) return;
    const int lane = threadIdx.x & 31;
    const int grp  = lane >> 4;     // 0: even edges, 1: odd edges
    const int l16  = lane & 15;
    const bool act = (D4 == 16) || (l16 < D4);
    const int s = g_start[warp];
    const int e = s + g_cnt[warp];

    float4 acc = make_float4(0.f, 0.f, 0.f, 0.f);
    int i = s + grp;
    // 2 edges in flight per group -> 4 per warp
    for (; i + 2 < e; i += 4) {
        int2 c0 = g_edge[i];
        int2 c1 = g_edge[i + 2];
        if (act) {
            float4 v0 = sup[(size_t)c0.x * D4 + l16];
            float4 v1 = sup[(size_t)c1.x * D4 + l16];
            float w0 = __int_as_float(c0.y);
            float w1 = __int_as_float(c1.y);
            acc.x = fmaf(v0.x, w0, acc.x); acc.y = fmaf(v0.y, w0, acc.y);
            acc.z = fmaf(v0.z, w0, acc.z); acc.w = fmaf(v0.w, w0, acc.w);
            acc.x = fmaf(v1.x, w1, acc.x); acc.y = fmaf(v1.y, w1, acc.y);
            acc.z = fmaf(v1.z, w1, acc.z); acc.w = fmaf(v1.w, w1, acc.w);
        }
    }
    if (i < e) {
        int2 c = g_edge[i];
        if (act) {
            float4 v = sup[(size_t)c.x * D4 + l16];
            float w = __int_as_float(c.y);
            acc.x = fmaf(v.x, w, acc.x); acc.y = fmaf(v.y, w, acc.y);
            acc.z = fmaf(v.z, w, acc.z); acc.w = fmaf(v.w, w, acc.w);
        }
    }

    // combine even/odd groups
    acc.x += __shfl_xor_sync(0xffffffffu, acc.x, 16);
    acc.y += __shfl_xor_sync(0xffffffffu, acc.y, 16);
    acc.z += __shfl_xor_sync(0xffffffffu, acc.z, 16);
    acc.w += __shfl_xor_sync(0xffffffffu, acc.w, 16);

    if (!LOGSM) {
        if (lane < D4) out[(size_t)warp * D4 + lane] = acc;
    } else {
        // 40 logits in lanes 0..9 (4 each); lanes 16..25 hold identical copies
        bool a10 = l16 < D4;
        float mv = a10 ? fmaxf(fmaxf(acc.x, acc.y), fmaxf(acc.z, acc.w)) : -INFINITY;
        #pragma unroll
        for (int o = 16; o; o >>= 1) mv = fmaxf(mv, __shfl_xor_sync(0xffffffffu, mv, o));
        float sv = a10 ? (expf(acc.x - mv) + expf(acc.y - mv) +
                          expf(acc.z - mv) + expf(acc.w - mv)) : 0.f;
        if (grp == 1) sv = 0.f;   // mask duplicate copies so each logit counts once
        #pragma unroll
        for (int o = 16; o; o >>= 1) sv += __shfl_xor_sync(0xffffffffu, sv, o);
        float ls = mv + logf(sv);
        if (lane < D4)
            out[(size_t)warp * D4 + lane] =
                make_float4(acc.x - ls, acc.y - ls, acc.z - ls, acc.w - ls);
    }
}

// ---------------------------------------------------------------------------
// Split-bf16 tensor-core GEMM (fp32 in/out; rel_err ~2e-6)
// ---------------------------------------------------------------------------
#define SROW 24

__device__ __forceinline__ unsigned pack_bf16(float a, float b) {
    __nv_bfloat162 t = __floats2bfloat162_rn(a, b);
    return *reinterpret_cast<unsigned*>(&t);
}

__device__ __forceinline__ void mma16816(float* c, const unsigned* a, const unsigned* b) {
    asm volatile(
        "mma.sync.aligned.m16n8k16.row.col.f32.bf16.bf16.f32 "
        "{%0,%1,%2,%3}, {%4,%5,%6,%7}, {%8,%9}, {%0,%1,%2,%3};"
        : "+f"(c[0]), "+f"(c[1]), "+f"(c[2]), "+f"(c[3])
        : "r"(a[0]), "r"(a[1]), "r"(a[2]), "r"(a[3]), "r"(b[0]), "r"(b[1]));
}

template <bool RELU>
__global__ __launch_bounds__(256) void gemm_mma_kernel(
    const float* __restrict__ A, const float* __restrict__ B,
    const float* __restrict__ bias, float* __restrict__ C,
    int M, int K, int N)
{
    __shared__ __nv_bfloat16 Ah[2][128 * SROW], Al[2][128 * SROW];
    __shared__ __nv_bfloat16 Bh[2][64 * SROW],  Bl[2][64 * SROW];

    const int tid  = threadIdx.x;
    const int m0   = blockIdx.x * 128;
    const int wid  = tid >> 5;
    const int lane = tid & 31;
    const int wm = (wid & 3) * 32;
    const int wn = (wid >> 2) * 32;
    const int qm = lane >> 2;
    const int qk = lane & 3;

    const int arow = tid >> 1;
    const int akh  = (tid & 1) * 8;
    const bool aok = (m0 + arow) < M;
    const float* Aptr = A + (size_t)(m0 + arow) * K + akh;

    const int bk = tid >> 4;
    const int bn = (tid * 4) & 63;

    float av[8];
    float bv[4];
    float acc[2][4][4] = {};

    const int S = K / 16;

    auto load_regs = [&](int k0) {
        if (aok) {
            float4 v0 = *reinterpret_cast<const float4*>(Aptr + k0);
            float4 v1 = *reinterpret_cast<const float4*>(Aptr + k0 + 4);
            av[0] = v0.x; av[1] = v0.y; av[2] = v0.z; av[3] = v0.w;
            av[4] = v1.x; av[5] = v1.y; av[6] = v1.z; av[7] = v1.w;
            if (RELU) {
                #pragma unroll
                for (int i = 0; i < 8; i++) av[i] = fmaxf(av[i], 0.f);
            }
        } else {
            #pragma unroll
            for (int i = 0; i < 8; i++) av[i] = 0.f;
        }
        #pragma unroll
        for (int j = 0; j < 4; j++) {
            int n = bn + j;
            bv[j] = (n < N) ? B[(size_t)(k0 + bk) * N + n] : 0.f;
        }
    };

    auto store_stage = [&](int st) {
        float lo[8];
        unsigned h[4], l[4];
        #pragma unroll
        for (int i = 0; i < 8; i++) {
            __nv_bfloat16 hb = __float2bfloat16_rn(av[i]);
            lo[i] = av[i] - __bfloat162float(hb);
        }
        #pragma unroll
        for (int p = 0; p < 4; p++) {
            h[p] = pack_bf16(av[2 * p], av[2 * p + 1]);
            l[p] = pack_bf16(lo[2 * p], lo[2 * p + 1]);
        }
        *reinterpret_cast<uint4*>(&Ah[st][arow * SROW + akh]) = make_uint4(h[0], h[1], h[2], h[3]);
        *reinterpret_cast<uint4*>(&Al[st][arow * SROW + akh]) = make_uint4(l[0], l[1], l[2], l[3]);
        #pragma unroll
        for (int j = 0; j < 4; j++) {
            __nv_bfloat16 hb = __float2bfloat16_rn(bv[j]);
            float lf = bv[j] - __bfloat162float(hb);
            Bh[st][(bn + j) * SROW + bk] = hb;
            Bl[st][(bn + j) * SROW + bk] = __float2bfloat16_rn(lf);
        }
    };

    load_regs(0);
    store_stage(0);
    __syncthreads();

    for (int s = 0; s < S; s++) {
        const int cur = s & 1;
        if (s + 1 < S) load_regs((s + 1) * 16);

        unsigned ah[2][4], al[2][4], bh[4][2], bl[4][2];
        #pragma unroll
        for (int i = 0; i < 2; i++) {
            int r = (wm + i * 16 + qm) * SROW;
            ah[i][0] = *reinterpret_cast<unsigned*>(&Ah[cur][r + qk * 2]);
            ah[i][1] = *reinterpret_cast<unsigned*>(&Ah[cur][r + 8 * SROW + qk * 2]);
            ah[i][2] = *reinterpret_cast<unsigned*>(&Ah[cur][r + 8 + qk * 2]);
            ah[i][3] = *reinterpret_cast<unsigned*>(&Ah[cur][r + 8 * SROW + 8 + qk * 2]);
            al[i][0] = *reinterpret_cast<unsigned*>(&Al[cur][r + qk * 2]);
            al[i][1] = *reinterpret_cast<unsigned*>(&Al[cur][r + 8 * SROW + qk * 2]);
            al[i][2] = *reinterpret_cast<unsigned*>(&Al[cur][r + 8 + qk * 2]);
            al[i][3] = *reinterpret_cast<unsigned*>(&Al[cur][r + 8 * SROW + 8 + qk * 2]);
        }
        #pragma unroll
        for (int j = 0; j < 4; j++) {
            int r = (wn + j * 8 + qm) * SROW;
            bh[j][0] = *reinterpret_cast<unsigned*>(&Bh[cur][r + qk * 2]);
            bh[j][1] = *reinterpret_cast<unsigned*>(&Bh[cur][r + 8 + qk * 2]);
            bl[j][0] = *reinterpret_cast<unsigned*>(&Bl[cur][r + qk * 2]);
            bl[j][1] = *reinterpret_cast<unsigned*>(&Bl[cur][r + 8 + qk * 2]);
        }

        #pragma unroll
        for (int i = 0; i < 2; i++)
            #pragma unroll
            for (int j = 0; j < 4; j++) {
                mma16816(acc[i][j], ah[i], bh[j]);
                mma16816(acc[i][j], ah[i], bl[j]);
                mma16816(acc[i][j], al[i], bh[j]);
            }

        if (s + 1 < S) {
            store_stage(cur ^ 1);
            __syncthreads();
        }
    }

    #pragma unroll
    for (int j = 0; j < 4; j++) {
        int c0 = wn + j * 8 + (lane & 3) * 2;
        if (c0 >= N) continue;
        float b0 = bias[c0], b1 = bias[c0 + 1];
        #pragma unroll
        for (int i = 0; i < 2; i++) {
            int r0 = m0 + wm + i * 16 + (lane >> 2);
            if (r0 < M) {
                float2 o = make_float2(acc[i][j][0] + b0, acc[i][j][1] + b1);
                *reinterpret_cast<float2*>(C + (size_t)r0 * N + c0) = o;
            }
            if (r0 + 8 < M) {
                float2 o = make_float2(acc[i][j][2] + b0, acc[i][j][3] + b1);
                *reinterpret_cast<float2*>(C + (size_t)(r0 + 8) * N + c0) = o;
            }
        }
    }
}

// ---------------------------------------------------------------------------
// launch: CSR ∥ GEMM1, then serial layers (R11 structure, float4 spmm).
// ---------------------------------------------------------------------------
extern "C" void kernel_launch(void* const* d_in, const int* in_sizes, int n_in,
                              void* d_out, int out_size)
{
    const float* x   = (const float*)d_in[0];
    const float* ew  = (const float*)d_in[1];
    const float* W1  = (const float*)d_in[2];
    const float* b1  = (const float*)d_in[3];
    const float* W2  = (const float*)d_in[4];
    const float* b2  = (const float*)d_in[5];
    const float* W3  = (const float*)d_in[6];
    const float* b3  = (const float*)d_in[7];
    const int*   row = (const int*)d_in[8];
    const int*   col = (const int*)d_in[9];
    float* out = (float*)d_out;

    float *bufA, *bufB;
    cudaGetSymbolAddress((void**)&bufA, g_bufA);
    cudaGetSymbolAddress((void**)&bufB, g_bufB);

    const int gemmBlocks = (NN + 127) / 128;          // 391
    const int edgeBlocks = (NE + 255) / 256;          // 3125
    const int rowBlocks  = (NN + 255) / 256;          // 196
    const int rowWarpBlocks = (NN * 32 + 255) / 256;  // 6250

    cudaStream_t s2;
    cudaStreamCreate(&s2);
    cudaEvent_t evFork, evCSR;
    cudaEventCreateWithFlags(&evFork, cudaEventDisableTiming);
    cudaEventCreateWithFlags(&evCSR,  cudaEventDisableTiming);

    cudaEventRecord(evFork, 0);
    cudaStreamWaitEvent(s2, evFork, 0);

    // s2: CSR build (concurrent with GEMM1)
    zero_cnt_kernel<<<rowBlocks, 256, 0, s2>>>();
    hist_rank_kernel<<<edgeBlocks, 256, 0, s2>>>(row);
    offsets_kernel<<<rowBlocks, 256, 0, s2>>>();
    scatter_kernel<<<edgeBlocks, 256, 0, s2>>>(row, col, ew);
    cudaEventRecord(evCSR, s2);

    // main: GEMM1 -> A
    gemm_mma_kernel<false><<<gemmBlocks, 256>>>(x, W1, b1, bufA, NN, 512, 64);
    cudaStreamWaitEvent(0, evCSR, 0);

    // layer 1: spmm A -> B
    spmm_csr_kernel<16, false><<<rowWarpBlocks, 256>>>(
        (const float4*)bufA, (float4*)bufB);
    // layer 2: gemm (relu) B -> A ; spmm A -> B
    gemm_mma_kernel<true><<<gemmBlocks, 256>>>(bufB, W2, b2, bufA, NN, 64, 64);
    spmm_csr_kernel<16, false><<<rowWarpBlocks, 256>>>(
        (const float4*)bufA, (float4*)bufB);
    // layer 3: gemm B -> A (40) ; spmm + log-softmax -> out
    gemm_mma_kernel<false><<<gemmBlocks, 256>>>(bufB, W3, b3, bufA, NN, 64, 40);
    spmm_csr_kernel<10, true><<<rowWarpBlocks, 256>>>(
        (const float4*)bufA, (float4*)out);

    cudaEventDestroy(evFork);
    cudaEventDestroy(evCSR);
    cudaStreamDestroy(s2);
}